// round 2
// baseline (speedup 1.0000x reference)
#include <cuda_runtime.h>
#include <math.h>

// Problem constants (EpochedFutureFill): B=256, T=32768, L=32768.
// n_fft = next_pow2(T+L-1) = 65536 = 256*256 (four-step FFT).
// Pack row pairs into complex signals: 128 signals of length 65536.
#define T_LEN   32768
#define N_FFT   65536
#define NSIG    128
#define SCALE_INV (1.0f / 65536.0f)

// Device-global scratch (no cudaMalloc allowed).
__device__ float2 d_scr[NSIG * N_FFT];   // 64 MB packed spectra workspace
__device__ float2 d_Htmp[N_FFT];         // filter intermediate (pass1 output)
__device__ float2 d_Hs[N_FFT];           // filter spectrum, layout [p][q] (positional)

__device__ __forceinline__ float2 cmul(float2 a, float2 b) {
    return make_float2(a.x * b.x - a.y * b.y, a.x * b.y + a.y * b.x);
}

// ---------------------------------------------------------------------------
// Stage-major twiddle table for 256-point radix-2 FFT.
// For DIF stage s (distance d=128>>s): needs W256^{j<<s}, j in [0, 128>>s).
// Stored contiguously per stage at offset 256 - (256>>s) -> unit-stride smem
// access within a warp. Total 255 float2 entries.
// ---------------------------------------------------------------------------
__device__ __forceinline__ void build_lut(float2* stab, int tid) {
    if (tid < 128) {
#pragma unroll
        for (int s = 0; s < 8; ++s) {
            const int d = 128 >> s;
            if (tid < d) {
                float sn, cs;
                // W256^e = exp(-2*pi*i*e/256), e = tid<<s  -> angle = -pi*e/128
                sincospif(-(float)(tid << s) / 128.0f, &sn, &cs);
                stab[(256 - (256 >> s)) + tid] = make_float2(cs, sn);
            }
        }
    }
}

// Long-twiddle factor tables: W_N^e = thi[e>>8] * tlo[e&255], e = n1*k2 < 65536.
// tlo[j] = cis(-pi*j/32768) = W_N^j ; thi[j] = cis(-pi*j/128) = W_N^{256 j}.
__device__ __forceinline__ void build_tw(float2* tlo, float2* thi, int tid) {
    float sn, cs;
    sincospif(-(float)tid / 32768.0f, &sn, &cs);
    tlo[tid] = make_float2(cs, sn);
    sincospif(-(float)tid / 128.0f, &sn, &cs);
    thi[tid] = make_float2(cs, sn);
}

// 256-point radix-2 DIF FFT, one warp, data in shared memory (re/im planes).
// Natural-order input, bit-reversed-position output. Forward sign (W = e^{-2pi i/256}).
__device__ __forceinline__ void fft256_dif(float* re, float* im,
                                           const float2* stab, int lane) {
#pragma unroll
    for (int s = 0; s < 8; ++s) {
        const int d = 128 >> s;
        const int off = 256 - (256 >> s);
#pragma unroll
        for (int t = 0; t < 4; ++t) {
            int b  = lane + (t << 5);          // butterfly index 0..127
            int j  = b & (d - 1);
            int i0 = ((b & ~(d - 1)) << 1) | j;
            int i1 = i0 + d;
            float ar = re[i0], ai = im[i0];
            float br = re[i1], bi = im[i1];
            float2 w = stab[off + j];          // W256^{j<<s}
            float xr = ar - br, xi = ai - bi;
            re[i0] = ar + br;  im[i0] = ai + bi;
            re[i1] = xr * w.x - xi * w.y;
            im[i1] = xr * w.y + xi * w.x;
        }
        __syncwarp();
    }
}

// 256-point radix-2 DIT inverse FFT (unnormalized), one warp.
// Bit-reversed-position input, natural-order output. Uses conj twiddles.
__device__ __forceinline__ void ifft256_dit(float* re, float* im,
                                            const float2* stab, int lane) {
#pragma unroll
    for (int s = 0; s < 8; ++s) {
        const int d = 1 << s;
        // needs W256^{j<<(7-s)}, j<2^s : that's exactly DIF-stage (7-s)'s table
        const int off = 256 - (256 >> (7 - s));
#pragma unroll
        for (int t = 0; t < 4; ++t) {
            int b  = lane + (t << 5);
            int j  = b & (d - 1);
            int i0 = ((b & ~(d - 1)) << 1) | j;
            int i1 = i0 + d;
            float2 w = stab[off + j];          // W256^{j<<(7-s)}; use conj
            float br = re[i1], bi = im[i1];
            float tr = br * w.x + bi * w.y;    // b * conj(w)
            float ti = bi * w.x - br * w.y;
            float ar = re[i0], ai = im[i0];
            re[i0] = ar + tr;  im[i0] = ai + ti;
            re[i1] = ar - tr;  im[i1] = ai - ti;
        }
        __syncwarp();
    }
}

// Shared tile: 8 rows (one per warp) x 256 points. ROWP=260: transpose-phase
// address j*260 + n1 -> bank (4j + n1) mod 32, all 32 distinct for j<8,
// n1 in 4-groups => conflict-free transposes.
#define ROWP 260

// ---------------------------------------------------------------------------
// Pass 1 (data): gather z[n] = x[2s][n] + i x[2s+1][n], n = n1 + 256*n2,
// FFT over n2 (per fixed n1), twiddle by W_N^{n1 * k2}, store d_scr[s][n1][p]
// (p = bitrev position of k2; twiddle uses actual k2 = rev(p)).
// Block: 256 threads = 8 warps handling n1 = n1b..n1b+7 for one signal s.
// ---------------------------------------------------------------------------
__global__ void __launch_bounds__(256) k_pass1(const float* __restrict__ x) {
    __shared__ float  sre[8][ROWP], sim[8][ROWP];
    __shared__ float2 stab[256];
    __shared__ float2 tlo[256], thi[256];
    const int tid = threadIdx.x;
    const int sgn = blockIdx.y;
    const int n1b = blockIdx.x * 8;

    build_lut(stab, tid);
    build_tw(tlo, thi, tid);

    const float* xr = x + (size_t)(2 * sgn)     * T_LEN;
    const float* xi = x + (size_t)(2 * sgn + 1) * T_LEN;
#pragma unroll
    for (int it = 0; it < 4; ++it) {
        int idx = tid + it * 256;        // 1024 = 8 * 128
        int n1l = idx & 7, n2 = idx >> 3;     // n2 in [0,128)
        int g = n1b + n1l + 256 * n2;         // coalesced 32B chunks
        sre[n1l][n2] = xr[g];
        sim[n1l][n2] = xi[g];
        sre[n1l][n2 + 128] = 0.0f;            // zero pad [T, N)
        sim[n1l][n2 + 128] = 0.0f;
    }
    __syncthreads();

    const int w = tid >> 5, lane = tid & 31;
    fft256_dif(sre[w], sim[w], stab, lane);

    const int n1 = n1b + w;
    float2* out = d_scr + (size_t)sgn * N_FFT + (size_t)n1 * 256;
#pragma unroll
    for (int k = 0; k < 8; ++k) {
        int p  = lane + 32 * k;
        int k2 = __brev(p) >> 24;                    // actual k2 at position p
        int e  = n1 * k2;                            // < 65536 always
        float2 wt = cmul(thi[e >> 8], tlo[e & 255]); // W_N^{n1*k2}
        float a = sre[w][p], b = sim[w][p];
        out[p] = make_float2(a * wt.x - b * wt.y, a * wt.y + b * wt.x);
    }
}

// ---------------------------------------------------------------------------
// Pass 2 (data, fused): for each k2-position p: forward FFT over n1,
// multiply by filter spectrum Hs[p][q] (same positional convention),
// inverse FFT over k1, un-twiddle by W_N^{-n1*k2}. In-place on d_scr.
// Block handles 8 consecutive p for one signal; tiled smem transpose for
// coalesced 64B global chunks.
// ---------------------------------------------------------------------------
__global__ void __launch_bounds__(256) k_pass2() {
    __shared__ float  sre[8][ROWP], sim[8][ROWP];
    __shared__ float2 stab[256];
    __shared__ float2 tlo[256], thi[256];
    const int tid = threadIdx.x;
    const int sgn = blockIdx.y;
    const int pb  = blockIdx.x * 8;

    build_lut(stab, tid);
    build_tw(tlo, thi, tid);

    float2* base = d_scr + (size_t)sgn * N_FFT;
#pragma unroll
    for (int it = 0; it < 8; ++it) {
        int idx = tid + it * 256;        // 2048 = 8 * 256
        int j = idx & 7, n1 = idx >> 3;
        float2 v = base[(size_t)n1 * 256 + pb + j];   // 64B chunks
        sre[j][n1] = v.x;  sim[j][n1] = v.y;
    }
    __syncthreads();

    const int w = tid >> 5, lane = tid & 31;
    fft256_dif(sre[w], sim[w], stab, lane);           // over n1 -> positions q

    const int p = pb + w;
    const float2* H = d_Hs + (size_t)p * 256;
#pragma unroll
    for (int k = 0; k < 8; ++k) {
        int q = lane + 32 * k;
        float2 h = H[q];
        float a = sre[w][q], b = sim[w][q];
        sre[w][q] = a * h.x - b * h.y;
        sim[w][q] = a * h.y + b * h.x;
    }
    __syncwarp();

    ifft256_dit(sre[w], sim[w], stab, lane);          // -> natural n1

    const int k2 = __brev(p) >> 24;
#pragma unroll
    for (int k = 0; k < 8; ++k) {
        int n1 = lane + 32 * k;
        int e  = n1 * k2;                             // < 65536
        float2 wt = cmul(thi[e >> 8], tlo[e & 255]);  // W_N^{+n1*k2}; apply conj
        float a = sre[w][n1], b = sim[w][n1];
        sre[w][n1] = a * wt.x + b * wt.y;             // * conj(wt) = W_N^{-n1*k2}
        sim[w][n1] = b * wt.x - a * wt.y;
    }
    __syncthreads();

#pragma unroll
    for (int it = 0; it < 8; ++it) {
        int idx = tid + it * 256;
        int j = idx & 7, n1 = idx >> 3;
        base[(size_t)n1 * 256 + pb + j] = make_float2(sre[j][n1], sim[j][n1]);
    }
}

// ---------------------------------------------------------------------------
// Pass 3 (data): inverse FFT over k2 (bit-rev positions -> natural n2),
// scale by 1/N, unpack re/im into the two output rows (only n2 < 128, i.e.
// time index n = n1 + 256*n2 < T). Tiled store for 32B-sector coalescing.
// ---------------------------------------------------------------------------
__global__ void __launch_bounds__(256) k_pass3(float* __restrict__ y) {
    __shared__ float  sre[8][ROWP], sim[8][ROWP];
    __shared__ float2 stab[256];
    const int tid = threadIdx.x;
    const int sgn = blockIdx.y;
    const int n1b = blockIdx.x * 8;

    build_lut(stab, tid);

    const int w = tid >> 5, lane = tid & 31;
    const float2* row = d_scr + (size_t)sgn * N_FFT + (size_t)(n1b + w) * 256;
#pragma unroll
    for (int k = 0; k < 8; ++k) {
        int p = lane + 32 * k;
        float2 v = row[p];                            // contiguous per warp
        sre[w][p] = v.x;  sim[w][p] = v.y;
    }
    __syncthreads();   // lut ready + tile loaded

    ifft256_dit(sre[w], sim[w], stab, lane);
    __syncthreads();

    float* yr = y + (size_t)(2 * sgn)     * T_LEN;
    float* yi = y + (size_t)(2 * sgn + 1) * T_LEN;
#pragma unroll
    for (int it = 0; it < 4; ++it) {
        int idx = tid + it * 256;        // 1024 = 8 * 128
        int n1l = idx & 7, n2 = idx >> 3;             // n2 < 128 -> n < T
        int g = n1b + n1l + 256 * n2;
        yr[g] = sre[n1l][n2] * SCALE_INV;
        yi[g] = sim[n1l][n2] * SCALE_INV;
    }
}

// ---------------------------------------------------------------------------
// Filter pass 1: same as data pass 1 but real input (imag = 0), one signal.
// Output d_Htmp[n1*256 + p].
// ---------------------------------------------------------------------------
__global__ void __launch_bounds__(256) k_fpass1(const float* __restrict__ filt) {
    __shared__ float  sre[8][ROWP], sim[8][ROWP];
    __shared__ float2 stab[256];
    __shared__ float2 tlo[256], thi[256];
    const int tid = threadIdx.x;
    const int n1b = blockIdx.x * 8;

    build_lut(stab, tid);
    build_tw(tlo, thi, tid);

#pragma unroll
    for (int it = 0; it < 4; ++it) {
        int idx = tid + it * 256;
        int n1l = idx & 7, n2 = idx >> 3;
        int g = n1b + n1l + 256 * n2;                 // < 32768 = L
        sre[n1l][n2] = filt[g];
        sim[n1l][n2] = 0.0f;
        sre[n1l][n2 + 128] = 0.0f;
        sim[n1l][n2 + 128] = 0.0f;
    }
    __syncthreads();

    const int w = tid >> 5, lane = tid & 31;
    fft256_dif(sre[w], sim[w], stab, lane);

    const int n1 = n1b + w;
    float2* out = d_Htmp + (size_t)n1 * 256;
#pragma unroll
    for (int k = 0; k < 8; ++k) {
        int p  = lane + 32 * k;
        int k2 = __brev(p) >> 24;
        int e  = n1 * k2;
        float2 wt = cmul(thi[e >> 8], tlo[e & 255]);
        float a = sre[w][p], b = sim[w][p];
        out[p] = make_float2(a * wt.x - b * wt.y, a * wt.y + b * wt.x);
    }
}

// ---------------------------------------------------------------------------
// Filter pass 2: forward FFT over n1 for each p; store spectrum positionally:
// d_Hs[p*256 + q]. (No multiply/inverse — this IS the H used by data pass 2.)
// ---------------------------------------------------------------------------
__global__ void __launch_bounds__(256) k_fpass2() {
    __shared__ float  sre[8][ROWP], sim[8][ROWP];
    __shared__ float2 stab[256];
    const int tid = threadIdx.x;
    const int pb  = blockIdx.x * 8;

    build_lut(stab, tid);

#pragma unroll
    for (int it = 0; it < 8; ++it) {
        int idx = tid + it * 256;
        int j = idx & 7, n1 = idx >> 3;
        float2 v = d_Htmp[(size_t)n1 * 256 + pb + j];
        sre[j][n1] = v.x;  sim[j][n1] = v.y;
    }
    __syncthreads();

    const int w = tid >> 5, lane = tid & 31;
    fft256_dif(sre[w], sim[w], stab, lane);

    float2* out = d_Hs + (size_t)(pb + w) * 256;
#pragma unroll
    for (int k = 0; k < 8; ++k) {
        int q = lane + 32 * k;
        out[q] = make_float2(sre[w][q], sim[w][q]);
    }
}

// ---------------------------------------------------------------------------
// Launch: filter spectrum first, then the 3 data passes. All graph-capturable
// (plain kernel launches, no allocs/syncs/memcpys).
// ---------------------------------------------------------------------------
extern "C" void kernel_launch(void* const* d_in, const int* in_sizes, int n_in,
                              void* d_out, int out_size) {
    (void)n_in; (void)out_size;
    const float* x    = (const float*)d_in[0];   // (256, 32768) fp32
    const float* filt = (const float*)d_in[1];   // (1, 32768)   fp32
    if (in_sizes && in_sizes[0] == T_LEN && n_in >= 2) {  // safety: swapped order
        x    = (const float*)d_in[1];
        filt = (const float*)d_in[0];
    }
    float* y = (float*)d_out;                    // (256, 32768) fp32

    k_fpass1<<<32, 256>>>(filt);
    k_fpass2<<<32, 256>>>();
    k_pass1 <<<dim3(32, NSIG), 256>>>(x);
    k_pass2 <<<dim3(32, NSIG), 256>>>();
    k_pass3 <<<dim3(32, NSIG), 256>>>(y);
}

// round 8
// speedup vs baseline: 1.8633x; 1.8633x over previous
#include <cuda_runtime.h>
#include <math.h>

// EpochedFutureFill: B=256, T=32768, L=32768 -> n_fft = 65536 = 256*256.
// Row pairs packed as complex: 128 signals of length 65536. Four-step FFT:
//   pass1: FFT over n2 (column), long twiddle, write scrambled-p rows
//   pass2: FFT over n1, positional multiply by filter spectrum, inverse FFT,
//          un-twiddle (all per k2-position row)
//   pass3: inverse FFT over k2, scale, unpack to output rows
// All 256-pt FFTs are register-resident per warp (8 float2/thread,
// point n = 32k + lane); distances 128/64/32 are intra-thread, 16..1 via
// __shfl_xor. Shared memory only for coalescing transposes + twiddle LUTs.
// 64 MB scratch fits in L2 (~126 MB), so inter-pass traffic stays at LTS.
#define T_LEN   32768
#define N_FFT   65536
#define NSIG    128
#define SCALE_INV (1.0f / 65536.0f)

__device__ float2 d_scr[NSIG * N_FFT];   // 64 MB workspace
__device__ float2 d_Htmp[N_FFT];         // filter intermediate
__device__ float2 d_Hs[N_FFT];           // filter spectrum [p][q] positional

__device__ __forceinline__ float2 cmul(float2 a, float2 b) {
    return make_float2(a.x * b.x - a.y * b.y, a.x * b.y + a.y * b.x);
}
__device__ __forceinline__ float2 cmulc(float2 a, float2 b) {  // a * conj(b)
    return make_float2(a.x * b.x + a.y * b.y, a.y * b.x - a.x * b.y);
}

// Forward DIF butterfly: (a,b) -> (a+b, (a-b)*w)
__device__ __forceinline__ void bfly_f(float2& lo, float2& hi, float2 w) {
    float2 a = lo, b = hi;
    lo = make_float2(a.x + b.x, a.y + b.y);
    hi = cmul(make_float2(a.x - b.x, a.y - b.y), w);
}
// Inverse butterfly (exact reverse, factor 2): t = hi*conj(w); (lo+t, lo-t)
__device__ __forceinline__ void bfly_i(float2& lo, float2& hi, float2 w) {
    float2 t = cmulc(hi, w);
    float2 a = lo;
    lo = make_float2(a.x + t.x, a.y + t.y);
    hi = make_float2(a.x - t.x, a.y - t.y);
}

// t256[j] = W_256^j = cis(-pi*j/128). Also serves as W_N^{256*j}.
__device__ __forceinline__ void build_t256(float2* t256, int tid) {
    float sn, cs;
    sincospif(-(float)tid / 128.0f, &sn, &cs);
    t256[tid] = make_float2(cs, sn);
}
// tlo[j] = W_N^j = cis(-pi*j/32768)
__device__ __forceinline__ void build_tlo(float2* tlo, int tid) {
    float sn, cs;
    sincospif(-(float)tid / 32768.0f, &sn, &cs);
    tlo[tid] = make_float2(cs, sn);
}

// 256-pt forward DIF FFT, warp-register-resident. v[k] = point 32k+lane.
// Natural input order, bit-reversed-position output (positional in-place).
__device__ __forceinline__ void fft256_reg(float2 v[8],
                                           const float2* __restrict__ t256,
                                           int lane) {
    // d=128: pairs (k, k+4), W_256^{32k+lane}
#pragma unroll
    for (int k = 0; k < 4; ++k) bfly_f(v[k], v[k + 4], t256[32 * k + lane]);
    // d=64: pairs (0,2),(1,3),(4,6),(5,7); W_256^{64*(k&1)+2*lane}
    {
        float2 w0 = t256[2 * lane], w1 = t256[64 + 2 * lane];
        bfly_f(v[0], v[2], w0); bfly_f(v[1], v[3], w1);
        bfly_f(v[4], v[6], w0); bfly_f(v[5], v[7], w1);
    }
    // d=32: pairs (even k, k+1); W_256^{4*lane}
    {
        float2 w = t256[4 * lane];
        bfly_f(v[0], v[1], w); bfly_f(v[2], v[3], w);
        bfly_f(v[4], v[5], w); bfly_f(v[6], v[7], w);
    }
    // d=16,8,4,2,1: cross-lane via shfl_xor; twiddle depends on lane only
#pragma unroll
    for (int s = 0; s < 5; ++s) {
        const int d = 16 >> s;
        float2 w = t256[(lane & (d - 1)) * (128 / d)];
        const bool up = (lane & d) != 0;
#pragma unroll
        for (int k = 0; k < 8; ++k) {
            float tr = __shfl_xor_sync(0xffffffffu, v[k].x, d);
            float ti = __shfl_xor_sync(0xffffffffu, v[k].y, d);
            if (up) v[k] = cmul(make_float2(tr - v[k].x, ti - v[k].y), w);
            else    { v[k].x += tr; v[k].y += ti; }
        }
    }
}

// 256-pt inverse (unnormalized, x256): exact reverse of fft256_reg's graph.
// Bit-reversed-position input -> natural order output.
__device__ __forceinline__ void ifft256_reg(float2 v[8],
                                            const float2* __restrict__ t256,
                                            int lane) {
#pragma unroll
    for (int s = 0; s < 5; ++s) {
        const int d = 1 << s;
        float2 w = t256[(lane & (d - 1)) * (128 / d)];
        const bool up = (lane & d) != 0;
#pragma unroll
        for (int k = 0; k < 8; ++k) {
            float2 x = v[k];
            if (up) x = cmulc(x, w);               // pre-multiply diff term
            float tr = __shfl_xor_sync(0xffffffffu, x.x, d);
            float ti = __shfl_xor_sync(0xffffffffu, x.y, d);
            v[k] = up ? make_float2(tr - x.x, ti - x.y)
                      : make_float2(x.x + tr, x.y + ti);
        }
    }
    {
        float2 w = t256[4 * lane];
        bfly_i(v[0], v[1], w); bfly_i(v[2], v[3], w);
        bfly_i(v[4], v[5], w); bfly_i(v[6], v[7], w);
    }
    {
        float2 w0 = t256[2 * lane], w1 = t256[64 + 2 * lane];
        bfly_i(v[0], v[2], w0); bfly_i(v[1], v[3], w1);
        bfly_i(v[4], v[6], w0); bfly_i(v[5], v[7], w1);
    }
#pragma unroll
    for (int k = 0; k < 4; ++k) bfly_i(v[k], v[k + 4], t256[32 * k + lane]);
}

// ---------------------------------------------------------------------------
// Pass 1: z[n] = x[2s][n] + i x[2s+1][n], n = n1 + 256*n2. FFT over n2,
// twiddle W_N^{n1*k2}, store d_scr[s][n1][p]. Tile only for load coalescing;
// zero-padded upper half never touches smem.
// ---------------------------------------------------------------------------
__global__ void __launch_bounds__(256) k_pass1(const float* __restrict__ x) {
    __shared__ float  sre[8][132], sim[8][132];   // 132 % 32 == 4: conflict-free
    __shared__ float2 t256[256], tlo[256];
    const int tid = threadIdx.x, sgn = blockIdx.y, n1b = blockIdx.x * 8;
    build_t256(t256, tid);
    build_tlo(tlo, tid);

    const float* __restrict__ xr = x + (size_t)(2 * sgn)     * T_LEN;
    const float* __restrict__ xi = x + (size_t)(2 * sgn + 1) * T_LEN;
#pragma unroll
    for (int it = 0; it < 4; ++it) {
        int idx = tid + it * 256;              // 1024 = 8 * 128
        int n1l = idx & 7, n2 = idx >> 3;      // n2 in [0,128)
        int g = n1b + n1l + 256 * n2;          // coalesced 32B chunks
        sre[n1l][n2] = xr[g];
        sim[n1l][n2] = xi[g];
    }
    __syncthreads();

    const int w = tid >> 5, lane = tid & 31;
    float2 v[8];
#pragma unroll
    for (int k = 0; k < 4; ++k) {
        v[k]     = make_float2(sre[w][32 * k + lane], sim[w][32 * k + lane]);
        v[k + 4] = make_float2(0.f, 0.f);      // zero pad [T, N)
    }
    fft256_reg(v, t256, lane);

    const int n1 = n1b + w;
    float2* __restrict__ out = d_scr + (size_t)sgn * N_FFT + (size_t)n1 * 256;
#pragma unroll
    for (int k = 0; k < 8; ++k) {
        int p  = 32 * k + lane;
        int k2 = __brev(p) >> 24;              // actual k2 at position p
        int e  = n1 * k2;                      // < 65536
        float2 wt = cmul(t256[e >> 8], tlo[e & 255]);   // W_N^{n1*k2}
        out[p] = cmul(v[k], wt);
    }
}

// ---------------------------------------------------------------------------
// Pass 2 (fused): fwd FFT over n1, positional multiply by Hs[p][q],
// inverse FFT, un-twiddle W_N^{-n1*k2}. Tile for global coalescing only.
// ---------------------------------------------------------------------------
__global__ void __launch_bounds__(256) k_pass2() {
    __shared__ float  sre[8][260], sim[8][260];   // 260 % 32 == 4
    __shared__ float2 t256[256], tlo[256];
    const int tid = threadIdx.x, sgn = blockIdx.y, pb = blockIdx.x * 8;
    build_t256(t256, tid);
    build_tlo(tlo, tid);

    float2* __restrict__ base = d_scr + (size_t)sgn * N_FFT;
#pragma unroll
    for (int it = 0; it < 8; ++it) {
        int idx = tid + it * 256;              // 2048 = 8 * 256
        int j = idx & 7, n1 = idx >> 3;
        float2 t = base[(size_t)n1 * 256 + pb + j];   // 64B chunks
        sre[j][n1] = t.x;  sim[j][n1] = t.y;
    }
    __syncthreads();

    const int w = tid >> 5, lane = tid & 31;
    float2 v[8];
#pragma unroll
    for (int k = 0; k < 8; ++k)
        v[k] = make_float2(sre[w][32 * k + lane], sim[w][32 * k + lane]);
    __syncthreads();                           // reads done before overwrite

    fft256_reg(v, t256, lane);                 // over n1 -> positions q

    const int p = pb + w;
    const float2* __restrict__ H = d_Hs + (size_t)p * 256;
#pragma unroll
    for (int k = 0; k < 8; ++k) v[k] = cmul(v[k], H[32 * k + lane]);

    ifft256_reg(v, t256, lane);                // -> natural n1

    const int k2 = __brev(p) >> 24;
#pragma unroll
    for (int k = 0; k < 8; ++k) {
        int n1 = 32 * k + lane;
        int e  = n1 * k2;                      // < 65536
        float2 wt = cmul(t256[e >> 8], tlo[e & 255]);
        v[k] = cmulc(v[k], wt);                // * W_N^{-n1*k2}
    }

#pragma unroll
    for (int k = 0; k < 8; ++k) {
        sre[w][32 * k + lane] = v[k].x;
        sim[w][32 * k + lane] = v[k].y;
    }
    __syncthreads();
#pragma unroll
    for (int it = 0; it < 8; ++it) {
        int idx = tid + it * 256;
        int j = idx & 7, n1 = idx >> 3;
        base[(size_t)n1 * 256 + pb + j] = make_float2(sre[j][n1], sim[j][n1]);
    }
}

// ---------------------------------------------------------------------------
// Pass 3: inverse FFT over k2 (rows read coalesced straight into registers),
// scale 1/N, tile only for the transposed coalesced store (n2 < 128 kept).
// ---------------------------------------------------------------------------
__global__ void __launch_bounds__(256) k_pass3(float* __restrict__ y) {
    __shared__ float  sre[8][132], sim[8][132];
    __shared__ float2 t256[256];
    const int tid = threadIdx.x, sgn = blockIdx.y, n1b = blockIdx.x * 8;
    build_t256(t256, tid);

    const int w = tid >> 5, lane = tid & 31;
    const float2* __restrict__ row =
        d_scr + (size_t)sgn * N_FFT + (size_t)(n1b + w) * 256;
    float2 v[8];
#pragma unroll
    for (int k = 0; k < 8; ++k) v[k] = row[32 * k + lane];   // coalesced
    __syncthreads();                           // t256 ready

    ifft256_reg(v, t256, lane);                // natural n2 = 32k+lane

#pragma unroll
    for (int k = 0; k < 4; ++k) {              // only n2 < 128 -> n < T
        sre[w][32 * k + lane] = v[k].x * SCALE_INV;
        sim[w][32 * k + lane] = v[k].y * SCALE_INV;
    }
    __syncthreads();

    float* __restrict__ yr = y + (size_t)(2 * sgn)     * T_LEN;
    float* __restrict__ yi = y + (size_t)(2 * sgn + 1) * T_LEN;
#pragma unroll
    for (int it = 0; it < 4; ++it) {
        int idx = tid + it * 256;
        int n1l = idx & 7, n2 = idx >> 3;
        int g = n1b + n1l + 256 * n2;
        yr[g] = sre[n1l][n2];
        yi[g] = sim[n1l][n2];
    }
}

// ---------------------------------------------------------------------------
// Filter pass 1: real input, single signal -> d_Htmp[n1*256 + p].
// ---------------------------------------------------------------------------
__global__ void __launch_bounds__(256) k_fpass1(const float* __restrict__ filt) {
    __shared__ float  sre[8][132];
    __shared__ float2 t256[256], tlo[256];
    const int tid = threadIdx.x, n1b = blockIdx.x * 8;
    build_t256(t256, tid);
    build_tlo(tlo, tid);

#pragma unroll
    for (int it = 0; it < 4; ++it) {
        int idx = tid + it * 256;
        int n1l = idx & 7, n2 = idx >> 3;
        sre[n1l][n2] = filt[n1b + n1l + 256 * n2];   // < 32768 = L
    }
    __syncthreads();

    const int w = tid >> 5, lane = tid & 31;
    float2 v[8];
#pragma unroll
    for (int k = 0; k < 4; ++k) {
        v[k]     = make_float2(sre[w][32 * k + lane], 0.f);
        v[k + 4] = make_float2(0.f, 0.f);
    }
    fft256_reg(v, t256, lane);

    const int n1 = n1b + w;
    float2* __restrict__ out = d_Htmp + (size_t)n1 * 256;
#pragma unroll
    for (int k = 0; k < 8; ++k) {
        int p  = 32 * k + lane;
        int k2 = __brev(p) >> 24;
        int e  = n1 * k2;
        float2 wt = cmul(t256[e >> 8], tlo[e & 255]);
        out[p] = cmul(v[k], wt);
    }
}

// ---------------------------------------------------------------------------
// Filter pass 2: fwd FFT over n1 per p; store positionally d_Hs[p*256 + q].
// ---------------------------------------------------------------------------
__global__ void __launch_bounds__(256) k_fpass2() {
    __shared__ float  sre[8][260], sim[8][260];
    __shared__ float2 t256[256];
    const int tid = threadIdx.x, pb = blockIdx.x * 8;
    build_t256(t256, tid);

#pragma unroll
    for (int it = 0; it < 8; ++it) {
        int idx = tid + it * 256;
        int j = idx & 7, n1 = idx >> 3;
        float2 t = d_Htmp[(size_t)n1 * 256 + pb + j];
        sre[j][n1] = t.x;  sim[j][n1] = t.y;
    }
    __syncthreads();

    const int w = tid >> 5, lane = tid & 31;
    float2 v[8];
#pragma unroll
    for (int k = 0; k < 8; ++k)
        v[k] = make_float2(sre[w][32 * k + lane], sim[w][32 * k + lane]);
    fft256_reg(v, t256, lane);

    float2* __restrict__ out = d_Hs + (size_t)(pb + w) * 256;
#pragma unroll
    for (int k = 0; k < 8; ++k) out[32 * k + lane] = v[k];
}

// ---------------------------------------------------------------------------
extern "C" void kernel_launch(void* const* d_in, const int* in_sizes, int n_in,
                              void* d_out, int out_size) {
    (void)out_size;
    const float* x    = (const float*)d_in[0];   // (256, 32768) fp32
    const float* filt = (const float*)d_in[1];   // (1, 32768)   fp32
    if (in_sizes && n_in >= 2 && in_sizes[0] == T_LEN) {  // safety: swapped
        x    = (const float*)d_in[1];
        filt = (const float*)d_in[0];
    }
    float* y = (float*)d_out;                    // (256, 32768) fp32

    k_fpass1<<<32, 256>>>(filt);
    k_fpass2<<<32, 256>>>();
    k_pass1 <<<dim3(32, NSIG), 256>>>(x);
    k_pass2 <<<dim3(32, NSIG), 256>>>();
    k_pass3 <<<dim3(32, NSIG), 256>>>(y);
}